// round 15
// baseline (speedup 1.0000x reference)
#include <cuda_runtime.h>
#include <cuda_fp16.h>
#include <cstdint>

// Tropical (max-times) matvec: out[b, i] = max_j M[i, j] * x[b, j]
// B = 256, n = 2048.
//
// Launch sequence: memsetAsync(d_out, 0xFF) -> prep_m -> prep_x -> compute.
// prep_m / prep_x: fp32 -> half2, transposed into tiled j-major layout
//   g_MhT[i_tile][j2][i_local(128)], g_xhT[b_tile][j2][b_local(64)]
// so each compute stage is a CONTIGUOUS slab -> loader is pure cp.async.
// compute: persistent 444 CTAs (3/SM, 6 warps/SMSP), tile 128i x 64b,
// thread tile 8x4, BK2=8 (16 j per stage), 8192 stage-balanced work units,
// double-buffered smem filled by cp.async.cg (no LDG/STS, ~70 regs).
// Flush: atomicMax on the signed-int bit pattern of the fp32 max (outputs
// positive -> int order == float order); d_out preset to -1 by memset.

#define NN      2048
#define NB      256
#define NJ2     (NN / 2)             // 1024 half2 per row
#define BM      128
#define BN      64
#define BK2     8                    // half2 rows per stage (= 16 j)
#define N_TM    (NN / BM)            // 16
#define N_TB    (NB / BN)            // 4
#define N_TILES (N_TM * N_TB)        // 64
#define SPT     (NJ2 / BK2)          // 128 stages per tile
#define NSTAGES (N_TILES * SPT)      // 8192
#define NCTAS   444                  // 148 SMs x 3 CTAs
#define THREADS 256

// tiled j-major half2 copies (filled by prep kernels)
__device__ __align__(16) unsigned g_MhT[(size_t)N_TM * NJ2 * BM];   // 8.4 MB
__device__ __align__(16) unsigned g_xhT[(size_t)N_TB * NJ2 * BN];   // 1.05 MB

__device__ __forceinline__ unsigned h2u(__half2 h) {
    return *reinterpret_cast<unsigned*>(&h);
}
__device__ __forceinline__ __half2 u2h(unsigned u) {
    return *reinterpret_cast<__half2*>(&u);
}
__device__ __forceinline__ unsigned cvt2(float a, float b) {
    return h2u(__floats2half2_rn(a, b));
}

__device__ __forceinline__ void cp16(unsigned dst_smem, const void* src) {
    asm volatile("cp.async.cg.shared.global [%0], [%1], 16;"
                 :: "r"(dst_smem), "l"(src));
}
#define CP_COMMIT() asm volatile("cp.async.commit_group;")
#define CP_WAIT0()  asm volatile("cp.async.wait_group 0;" ::: "memory")

// ---- prep_m: M[2048,2048] fp32 -> g_MhT[16][1024][128] half2 (transposed) ----
// block = (i_tile, j_chunk of 64 j = 32 j2), 256 threads, smem transpose.
#define PT 132
__global__ __launch_bounds__(256, 1)
void prep_m_kernel(const float* __restrict__ M)
{
    __shared__ unsigned T[32 * PT];
    const int it  = blockIdx.x;          // 0..15
    const int jc  = blockIdx.y;          // 0..31
    const int tid = threadIdx.x;
    const int r0  = tid >> 4;            // 0..15
    const int f4  = tid & 15;            // float4 index within 64-j chunk

    #pragma unroll
    for (int k = 0; k < 8; k++) {
        const int r = r0 + k * 16;       // 0..127
        const float4 v = *((const float4*)(M + (size_t)(it * 128 + r) * NN + jc * 64) + f4);
        T[(f4 * 2 + 0) * PT + r] = cvt2(v.x, v.y);
        T[(f4 * 2 + 1) * PT + r] = cvt2(v.z, v.w);
    }
    __syncthreads();

    const int j2w = tid >> 3;            // 0..31
    const int u4  = tid & 7;
    uint4* dst = (uint4*)g_MhT + ((size_t)it * 1024 + jc * 32 + j2w) * 32;
    #pragma unroll
    for (int k = 0; k < 4; k++) {
        const int c = u4 + 8 * k;        // 0..31 uint4 within the 128-i row
        dst[c] = *(const uint4*)&T[j2w * PT + c * 4];
    }
}

// ---- prep_x: x[256,2048] fp32 -> g_xhT[4][1024][64] half2 (transposed) ----
#define PTX 68
__global__ __launch_bounds__(256, 1)
void prep_x_kernel(const float* __restrict__ x)
{
    __shared__ unsigned T[32 * PTX];
    const int bt  = blockIdx.x;          // 0..3
    const int jc  = blockIdx.y;          // 0..31
    const int tid = threadIdx.x;
    const int r0  = tid >> 4;            // 0..15
    const int f4  = tid & 15;

    #pragma unroll
    for (int k = 0; k < 4; k++) {
        const int r = r0 + k * 16;       // 0..63
        const float4 v = *((const float4*)(x + (size_t)(bt * 64 + r) * NN + jc * 64) + f4);
        T[(f4 * 2 + 0) * PTX + r] = cvt2(v.x, v.y);
        T[(f4 * 2 + 1) * PTX + r] = cvt2(v.z, v.w);
    }
    __syncthreads();

    const int j2w = tid >> 3;            // 0..31
    const int u4  = tid & 7;
    uint4* dst = (uint4*)g_xhT + ((size_t)bt * 1024 + jc * 32 + j2w) * 16;
    #pragma unroll
    for (int k = 0; k < 2; k++) {
        const int c = u4 + 8 * k;        // 0..15 uint4 within the 64-b row
        dst[c] = *(const uint4*)&T[j2w * PTX + c * 4];
    }
}

// ---- compute ----
__global__ __launch_bounds__(THREADS, 3)
void trop_mm_kernel(int* __restrict__ outw)
{
    __shared__ __align__(16) unsigned Ms[2][BK2 * BM];   // 2 x 4 KB
    __shared__ __align__(16) unsigned Xs[2][BK2 * BN];   // 2 x 2 KB

    const int tid = threadIdx.x;
    const int tx  = tid & 15;            // b-direction: 16 groups of TN=4
    const int ty  = tid >> 4;            // i-direction: 16 groups of TM=8

    const unsigned ms_base = (unsigned)__cvta_generic_to_shared(&Ms[0][0]);
    const unsigned xs_base = (unsigned)__cvta_generic_to_shared(&Xs[0][0]);

    // stage-balanced static partition over 8192 stages
    const int s_beg = (int)(((long)blockIdx.x * NSTAGES) / NCTAS);
    const int s_end = (int)(((long)(blockIdx.x + 1) * NSTAGES) / NCTAS);

    // issue cp.async copies for stage s into buffer buf
    auto issue_stage = [&](int s, int buf) {
        const int tile = s >> 7;                 // SPT = 128
        const int kt   = s & 127;
        const uint4* msrc = (const uint4*)g_MhT
            + ((size_t)(tile & (N_TM - 1)) * 1024 + kt * BK2) * (BM / 4) + tid;
        cp16(ms_base + buf * (BK2 * BM * 4) + tid * 16, msrc);
        if (tid < BK2 * BN / 4) {                // 128 threads
            const uint4* xsrc = (const uint4*)g_xhT
                + ((size_t)(tile >> 4) * 1024 + kt * BK2) * (BN / 4) + tid;
            cp16(xs_base + buf * (BK2 * BN * 4) + tid * 16, xsrc);
        }
        CP_COMMIT();
    };

    // prologue
    issue_stage(s_beg, 0);
    CP_WAIT0();
    __syncthreads();

    const __half2 NEG2 = __float2half2_rn(-65504.0f);
    __half2 acc[8][4];
    #pragma unroll
    for (int a = 0; a < 8; a++)
        #pragma unroll
        for (int c = 0; c < 4; c++)
            acc[a][c] = NEG2;

    int ls = 0;
    for (int s = s_beg; s < s_end; s++, ls++) {
        const int  buf       = ls & 1;
        const bool have_next = (s + 1 < s_end);

        if (have_next)
            issue_stage(s + 1, buf ^ 1);

        #pragma unroll
        for (int kk = 0; kk < BK2; kk++) {
            const uint4 mv0 = *(const uint4*)&Ms[buf][kk * BM + ty * 8];
            const uint4 mv1 = *(const uint4*)&Ms[buf][kk * BM + ty * 8 + 4];
            const uint4 xv4 = *(const uint4*)&Xs[buf][kk * BN + tx * 4];

            __half2 m2[8];
            m2[0] = u2h(mv0.x); m2[1] = u2h(mv0.y);
            m2[2] = u2h(mv0.z); m2[3] = u2h(mv0.w);
            m2[4] = u2h(mv1.x); m2[5] = u2h(mv1.y);
            m2[6] = u2h(mv1.z); m2[7] = u2h(mv1.w);
            __half2 x2[4];
            x2[0] = u2h(xv4.x); x2[1] = u2h(xv4.y);
            x2[2] = u2h(xv4.z); x2[3] = u2h(xv4.w);

            #pragma unroll
            for (int a = 0; a < 8; a++)
                #pragma unroll
                for (int c = 0; c < 4; c++)
                    acc[a][c] = __hmax2(acc[a][c], __hmul2(m2[a], x2[c]));
        }

        // flush at tile boundary or end of range:
        // atomicMax on int bit pattern (outputs positive -> order-preserving)
        if (((s & (SPT - 1)) == SPT - 1) || !have_next) {
            const int tile = s >> 7;
            const int i0   = (tile & (N_TM - 1)) * BM;
            const int b0   = (tile >> 4) * BN;
            #pragma unroll
            for (int c = 0; c < 4; c++) {
                const int b = b0 + tx * 4 + c;
                int* row = outw + (size_t)b * NN + i0 + ty * 8;
                #pragma unroll
                for (int a = 0; a < 8; a++) {
                    float2 f = __half22float2(acc[a][c]);
                    atomicMax(row + a, __float_as_int(fmaxf(f.x, f.y)));
                }
            }
            #pragma unroll
            for (int a = 0; a < 8; a++)
                #pragma unroll
                for (int c = 0; c < 4; c++)
                    acc[a][c] = NEG2;
        }

        if (have_next)
            CP_WAIT0();
        __syncthreads();
    }
}

extern "C" void kernel_launch(void* const* d_in, const int* in_sizes, int n_in,
                              void* d_out, int out_size)
{
    // x: [256, 2048] (524288), M: [2048, 2048] (4194304) — detect order defensively
    const float* x;
    const float* M;
    if (in_sizes[0] == NB * NN) { x = (const float*)d_in[0]; M = (const float*)d_in[1]; }
    else                        { x = (const float*)d_in[1]; M = (const float*)d_in[0]; }

    // 0xFFFFFFFF = int -1: smaller than any positive float's bit pattern.
    cudaMemsetAsync(d_out, 0xFF, (size_t)NB * NN * sizeof(int));

    prep_m_kernel<<<dim3(N_TM, 32), 256>>>(M);
    prep_x_kernel<<<dim3(N_TB, 32), 256>>>(x);

    trop_mm_kernel<<<NCTAS, THREADS>>>((int*)d_out);
}

// round 16
// speedup vs baseline: 1.0287x; 1.0287x over previous
#include <cuda_runtime.h>
#include <cuda_fp16.h>
#include <cstdint>

// Tropical (max-times) matvec: out[b, i] = max_j M[i, j] * x[b, j]
// B = 256, n = 2048.
//
// HYBRID: 296 CTAs; bid<148 run an fp16 half2 body (packed inputs from prep),
// bid>=148 run an fp32 body (original inputs, mul.rn.f32x2 + FMNMX).
// Classic placement maps bid and bid+148 to the same SM -> each SM gets one
// CTA of each flavor, spreading math across the fp16 SIMD path AND the
// fp32 fma/alu pipes. Tile split 45 (fp16) / 19 (fp32) of 64 output tiles.
// Flush: atomicMax on the signed-int bit pattern (outputs positive).
// d_out preset to -1 by cudaMemsetAsync. Launches: memset, prep, compute.

#define NN      2048
#define NB      256
#define NJ2     (NN / 2)             // 1024 half2 per row
#define BM      128
#define BN      64
#define N_TM    (NN / BM)            // 16
#define N_TB    (NB / BN)            // 4
#define N_TILES (N_TM * N_TB)        // 64

#define T16     45                   // tiles on the fp16 path (f = 0.703)
#define T32     (N_TILES - T16)      // 19 tiles on the fp32 path

#define BK2     16                   // fp16 stage: 16 half2 rows = 32 j
#define SPT16   (NJ2 / BK2)          // 64 stages per fp16 tile
#define N16     (T16 * SPT16)        // 2880 fp16 stages

#define BKF     16                   // fp32 stage: 16 j
#define SPT32   (NN / BKF)           // 128 stages per fp32 tile
#define N32     (T32 * SPT32)        // 2432 fp32 stages

#define HALF_GRID 148
#define NCTAS   (2 * HALF_GRID)
#define THREADS 256
#define MP      132                  // M smem pitch (4-byte units)
#define XP      68                   // X smem pitch

// packed half2 copies of M and x (j-packed), filled by prep_kernel
__device__ unsigned g_Mh[(size_t)NN * NJ2];   // 8.4 MB
__device__ unsigned g_xh[(size_t)NB * NJ2];   // 1.05 MB

__device__ __forceinline__ unsigned h2u(__half2 h) {
    return *reinterpret_cast<unsigned*>(&h);
}
__device__ __forceinline__ __half2 u2h(unsigned u) {
    return *reinterpret_cast<__half2*>(&u);
}

// ---- prep: convert fp32 M and x into j-packed half2 arrays ----
#define M_U4   (NN * NN / 8)         // 524288 uint4 of Mh
#define X_U4   (NB * NN / 8)         // 65536 uint4 of xh
__global__ __launch_bounds__(256, 1)
void prep_kernel(const float* __restrict__ x, const float* __restrict__ M)
{
    const int gid = blockIdx.x * 256 + threadIdx.x;
    const float4* src;
    uint4* dst;
    if (gid < M_U4) {
        src = (const float4*)M + (size_t)gid * 2;
        dst = (uint4*)g_Mh + gid;
    } else if (gid < M_U4 + X_U4) {
        const int g = gid - M_U4;
        src = (const float4*)x + (size_t)g * 2;
        dst = (uint4*)g_xh + g;
    } else {
        return;
    }
    float4 a = src[0], b = src[1];
    uint4 o;
    o.x = h2u(__floats2half2_rn(a.x, a.y));
    o.y = h2u(__floats2half2_rn(a.z, a.w));
    o.z = h2u(__floats2half2_rn(b.x, b.y));
    o.w = h2u(__floats2half2_rn(b.z, b.w));
    *dst = o;
}

// f32x2 helpers (fp32 path)
__device__ __forceinline__ unsigned long long dup_f32(float v) {
    unsigned long long r;
    unsigned int u = __float_as_uint(v);
    asm("mov.b64 %0, {%1, %1};" : "=l"(r) : "r"(u));
    return r;
}
__device__ __forceinline__ unsigned long long mul_f32x2(unsigned long long a,
                                                        unsigned long long b) {
    unsigned long long r;
    asm("mul.rn.f32x2 %0, %1, %2;" : "=l"(r) : "l"(a), "l"(b));
    return r;
}
__device__ __forceinline__ void unpack2(unsigned long long p, float& lo, float& hi) {
    unsigned int l, h;
    asm("mov.b64 {%0, %1}, %2;" : "=r"(l), "=r"(h) : "l"(p));
    lo = __uint_as_float(l);
    hi = __uint_as_float(h);
}

__global__ __launch_bounds__(THREADS, 2)
void trop_mm_kernel(const float* __restrict__ x, const float* __restrict__ M,
                    int* __restrict__ outw)
{
    // shared by both paths: identical byte layout (u32 half2-pairs vs f32)
    __shared__ __align__(16) unsigned MsU[2][16][MP];   // 16.9 KB
    __shared__ __align__(16) unsigned XsU[2][16][XP];   //  8.7 KB

    const int tid = threadIdx.x;
    const int tx  = tid & 15;            // b-direction: 16 groups of TN=4
    const int ty  = tid >> 4;            // i-direction: 16 groups of TM=8

    if (blockIdx.x < HALF_GRID) {
        // ================= fp16 path: tiles [0, T16) =================
        const int cta = blockIdx.x;
        const int s_beg = (int)(((long)cta * N16) / HALF_GRID);
        const int s_end = (int)(((long)(cta + 1) * N16) / HALF_GRID);

        const int m_row = tid >> 2;      // 0..63 -> rows m_row, m_row+64
        const int m_q   = tid & 3;
        const int x_row = tid >> 2;
        const int x_q   = tid & 3;

        uint4 mreg[2];
        uint4 xreg;

        auto load_stage = [&](int s) {
            const int tile = s >> 6;                 // SPT16 = 64
            const int kt   = s & 63;
            const int i0   = (tile & (N_TM - 1)) * BM;
            const int b0   = (tile >> 4) * BN;
            const unsigned* Mg = g_Mh + (size_t)(i0 + m_row) * NJ2 + kt * BK2 + m_q * 4;
            const unsigned* Xg = g_xh + (size_t)(b0 + x_row) * NJ2 + kt * BK2 + x_q * 4;
            mreg[0] = *(const uint4*)(Mg);
            mreg[1] = *(const uint4*)(Mg + (size_t)64 * NJ2);
            xreg    = *(const uint4*)(Xg);
        };
        auto store_stage = [&](int buf) {
            const unsigned* m0 = (const unsigned*)&mreg[0];
            const unsigned* m1 = (const unsigned*)&mreg[1];
            const unsigned* xf = (const unsigned*)&xreg;
            #pragma unroll
            for (int d = 0; d < 4; d++) {
                MsU[buf][m_q * 4 + d][m_row]      = m0[d];
                MsU[buf][m_q * 4 + d][m_row + 64] = m1[d];
                XsU[buf][x_q * 4 + d][x_row]      = xf[d];
            }
        };

        load_stage(s_beg);
        store_stage(0);
        __syncthreads();

        const __half2 NEG2 = __float2half2_rn(-65504.0f);
        __half2 acc[8][4];
        #pragma unroll
        for (int a = 0; a < 8; a++)
            #pragma unroll
            for (int c = 0; c < 4; c++)
                acc[a][c] = NEG2;

        int ls = 0;
        for (int s = s_beg; s < s_end; s++, ls++) {
            const int  buf       = ls & 1;
            const bool have_next = (s + 1 < s_end);

            if (have_next)
                load_stage(s + 1);

            #pragma unroll
            for (int kk = 0; kk < BK2; kk++) {
                const uint4 mv0 = *(const uint4*)&MsU[buf][kk][ty * 8];
                const uint4 mv1 = *(const uint4*)&MsU[buf][kk][ty * 8 + 4];
                const uint4 xv4 = *(const uint4*)&XsU[buf][kk][tx * 4];

                __half2 m2[8];
                m2[0] = u2h(mv0.x); m2[1] = u2h(mv0.y);
                m2[2] = u2h(mv0.z); m2[3] = u2h(mv0.w);
                m2[4] = u2h(mv1.x); m2[5] = u2h(mv1.y);
                m2[6] = u2h(mv1.z); m2[7] = u2h(mv1.w);
                __half2 x2[4];
                x2[0] = u2h(xv4.x); x2[1] = u2h(xv4.y);
                x2[2] = u2h(xv4.z); x2[3] = u2h(xv4.w);

                #pragma unroll
                for (int a = 0; a < 8; a++)
                    #pragma unroll
                    for (int c = 0; c < 4; c++)
                        acc[a][c] = __hmax2(acc[a][c], __hmul2(m2[a], x2[c]));
            }

            if (have_next)
                store_stage(buf ^ 1);

            if (((s & 63) == 63) || !have_next) {
                const int tile = s >> 6;
                const int i0   = (tile & (N_TM - 1)) * BM;
                const int b0   = (tile >> 4) * BN;
                #pragma unroll
                for (int c = 0; c < 4; c++) {
                    const int b = b0 + tx * 4 + c;
                    int* row = outw + (size_t)b * NN + i0 + ty * 8;
                    #pragma unroll
                    for (int a = 0; a < 8; a++) {
                        float2 f = __half22float2(acc[a][c]);
                        atomicMax(row + a, __float_as_int(fmaxf(f.x, f.y)));
                    }
                }
                #pragma unroll
                for (int a = 0; a < 8; a++)
                    #pragma unroll
                    for (int c = 0; c < 4; c++)
                        acc[a][c] = NEG2;
            }
            __syncthreads();
        }
    } else {
        // ================= fp32 path: tiles [T16, 64) =================
        const int cta = blockIdx.x - HALF_GRID;
        const int s_beg = (int)(((long)cta * N32) / HALF_GRID);
        const int s_end = (int)(((long)(cta + 1) * N32) / HALF_GRID);

        float (*Ms32)[16][MP] = (float (*)[16][MP])MsU;
        float (*Xs32)[16][XP] = (float (*)[16][XP])XsU;

        const int m_row = tid >> 2;      // 0..63 -> rows m_row, m_row+64
        const int m_j4  = (tid & 3) * 4;
        const int x_row = tid >> 2;
        const int x_j4  = (tid & 3) * 4;

        float4 mreg0, mreg1, xreg;

        auto load_stage = [&](int s) {
            const int tile = T16 + (s >> 7);          // SPT32 = 128
            const int kt   = s & 127;
            const int i0   = (tile & (N_TM - 1)) * BM;
            const int b0   = (tile >> 4) * BN;
            const float* Mg = M + (size_t)(i0 + m_row) * NN + kt * BKF + m_j4;
            const float* Xg = x + (size_t)(b0 + x_row) * NN + kt * BKF + x_j4;
            mreg0 = *(const float4*)(Mg);
            mreg1 = *(const float4*)(Mg + (size_t)64 * NN);
            xreg  = *(const float4*)(Xg);
        };
        auto store_stage = [&](int buf) {
            const float* m0 = (const float*)&mreg0;
            const float* m1 = (const float*)&mreg1;
            const float* xf = (const float*)&xreg;
            #pragma unroll
            for (int d = 0; d < 4; d++) {
                Ms32[buf][m_j4 + d][m_row]      = m0[d];
                Ms32[buf][m_j4 + d][m_row + 64] = m1[d];
                Xs32[buf][x_j4 + d][x_row]      = xf[d];
            }
        };

        load_stage(s_beg);
        store_stage(0);
        __syncthreads();

        const float NEGF = -3.0e38f;
        float acc[8][4];
        #pragma unroll
        for (int a = 0; a < 8; a++)
            #pragma unroll
            for (int c = 0; c < 4; c++)
                acc[a][c] = NEGF;

        int ls = 0;
        for (int s = s_beg; s < s_end; s++, ls++) {
            const int  buf       = ls & 1;
            const bool have_next = (s + 1 < s_end);

            if (have_next)
                load_stage(s + 1);

            #pragma unroll
            for (int kk = 0; kk < BKF; kk++) {
                const float* msrc = &Ms32[buf][kk][ty * 8];
                ulonglong2 mA = *(const ulonglong2*)(msrc);      // (m0,m1),(m2,m3)
                ulonglong2 mB = *(const ulonglong2*)(msrc + 4);  // (m4,m5),(m6,m7)
                float4 xv = *(const float4*)&Xs32[buf][kk][tx * 4];

                unsigned long long xx[4];
                xx[0] = dup_f32(xv.x);
                xx[1] = dup_f32(xv.y);
                xx[2] = dup_f32(xv.z);
                xx[3] = dup_f32(xv.w);
                unsigned long long mp[4] = {mA.x, mA.y, mB.x, mB.y};

                #pragma unroll
                for (int q = 0; q < 4; q++)
                    #pragma unroll
                    for (int c = 0; c < 4; c++) {
                        float lo, hi;
                        unpack2(mul_f32x2(mp[q], xx[c]), lo, hi);
                        acc[2 * q + 0][c] = fmaxf(acc[2 * q + 0][c], lo);
                        acc[2 * q + 1][c] = fmaxf(acc[2 * q + 1][c], hi);
                    }
            }

            if (have_next)
                store_stage(buf ^ 1);

            if (((s & 127) == 127) || !have_next) {
                const int tile = T16 + (s >> 7);
                const int i0   = (tile & (N_TM - 1)) * BM;
                const int b0   = (tile >> 4) * BN;
                #pragma unroll
                for (int c = 0; c < 4; c++) {
                    const int b = b0 + tx * 4 + c;
                    int* row = outw + (size_t)b * NN + i0 + ty * 8;
                    #pragma unroll
                    for (int a = 0; a < 8; a++)
                        atomicMax(row + a, __float_as_int(acc[a][c]));
                }
                #pragma unroll
                for (int a = 0; a < 8; a++)
                    #pragma unroll
                    for (int c = 0; c < 4; c++)
                        acc[a][c] = NEGF;
            }
            __syncthreads();
        }
    }
}

extern "C" void kernel_launch(void* const* d_in, const int* in_sizes, int n_in,
                              void* d_out, int out_size)
{
    // x: [256, 2048] (524288), M: [2048, 2048] (4194304) — detect order defensively
    const float* x;
    const float* M;
    if (in_sizes[0] == NB * NN) { x = (const float*)d_in[0]; M = (const float*)d_in[1]; }
    else                        { x = (const float*)d_in[1]; M = (const float*)d_in[0]; }

    // 0xFFFFFFFF = int -1: smaller than any positive float's bit pattern.
    cudaMemsetAsync(d_out, 0xFF, (size_t)NB * NN * sizeof(int));

    const int prep_blocks = (M_U4 + X_U4 + 255) / 256;   // 2304
    prep_kernel<<<prep_blocks, 256>>>(x, M);

    trop_mm_kernel<<<NCTAS, THREADS>>>(x, M, (int*)d_out);
}